// round 1
// baseline (speedup 1.0000x reference)
#include <cuda_runtime.h>

// Black_oil PINO residual, GB300 sm_103a.
// Shapes: [B=8, T=10, NZ=4, NX=128, NY=128], row-major, y contiguous.
// d_in order: pressure, perm, Q, Qw, Time, Pini(unused), Phi, Swini(scalar), water_sat.
// d_out: [p_loss (N floats) | s_loss (N floats)], N = 5,242,880.

#define TSTRIDE 65536   // NZ*NX*NY = 4*128*128

__global__ __launch_bounds__(256)
void blackoil_kernel(const float* __restrict__ pr,
                     const float* __restrict__ perm,
                     const float* __restrict__ Q,
                     const float* __restrict__ Qw,
                     const float* __restrict__ Tm,
                     const float* __restrict__ Phi,
                     const float* __restrict__ Swini,
                     const float* __restrict__ ws,
                     float* __restrict__ out,
                     int N)
{
    int idx = blockIdx.x * blockDim.x + threadIdx.x;
    if (idx >= N) return;

    const int y = idx & 127;
    const int x = (idx >> 7) & 127;
    const int t = (idx >> 16) % 10;          // (b*10 + t) % 10
    const int idx0 = idx - t * TSTRIDE;      // same (b,z,x,y) at t=0

    // replicate-padded central stencil offsets (branch-free clamp)
    const int oxm = (x > 0)   ? -128 : 0;
    const int oxp = (x < 127) ?  128 : 0;
    const int oym = (y > 0)   ?   -1 : 0;
    const int oyp = (y < 127) ?    1 : 0;

    // ---- pressure stencil, u = p * 1000 ----
    const float uc  = pr[idx]       * 1000.0f;
    const float uxm = pr[idx + oxm] * 1000.0f;
    const float uxp = pr[idx + oxp] * 1000.0f;
    const float uym = pr[idx + oym] * 1000.0f;
    const float uyp = pr[idx + oyp] * 1000.0f;

    // d1: (f-b)*(0.5/h), h = 1/128 -> *64 ; d2: (f-2c+b)/h^2 -> *16384
    const float dudx = (uxp - uxm) * 64.0f;
    const float dudy = (uyp - uym) * 64.0f;
    const float d2ux = (uxp - 2.0f * uc + uxm) * 16384.0f;
    const float d2uy = (uyp - 2.0f * uc + uym) * 16384.0f;

    // ---- t=0 mobility-field derivatives (scalar mobility * perm[t=0] stencil) ----
    const float s0  = Swini[0];
    const float S0  = (s0 - 0.1f) * 1.25f;          // (s - SWI)/(1 - SWI - SWR)
    const float Mw0 = S0 * S0;                       // /(UW*BW)=1
    const float Mo0 = (1.0f - S0) * (1.0f - S0) * (1.0f / 2.75f); // /(UO*BO)
    const float cM  = Mw0 + Mo0;
    const float cW  = Mw0;

    const float p0xm = perm[idx0 + oxm];
    const float p0xp = perm[idx0 + oxp];
    const float p0ym = perm[idx0 + oym];
    const float p0yp = perm[idx0 + oyp];
    // a = 500*perm ; d1 -> (f-b)*64*500
    const float da0dx = (p0xp - p0xm) * 32000.0f;
    const float da0dy = (p0yp - p0ym) * 32000.0f;
    const float dcdx = cM * da0dx, dcdy = cM * da0dy;
    const float dadx = cW * da0dx, dady = cW * da0dy;

    // ---- current-t mobilities from prior saturation ----
    const float prior = (t == 0) ? s0 : ws[idx - TSTRIDE];
    const float sat   = ws[idx];
    const float dsw   = fmaxf(sat - prior, 0.001f);

    const float S  = (prior - 0.1f) * 1.25f;
    const float Mw = S * S;
    const float Mo = (1.0f - S) * (1.0f - S) * (1.0f / 2.75f);
    const float aP  = 500.0f * perm[idx];
    const float a1  = (Mw + Mo) * aP;
    const float a1w = Mw * aP;

    // ---- sources / misc fields ----
    const float fin  = Q[idx]  * 5000.0f;
    const float finw = Qw[idx] * 5000.0f;
    const float dta  = Tm[idx] * 6000.0f;
    const float phi  = Phi[idx];

    const float sc = 7.8125e-8f;   // dxf * 1e-5 = (1/128)*1e-5
    const float p_loss = sc * (fin + dcdx * dudx + a1 * d2ux + dcdy * dudy + a1 * d2uy);
    const float flux   = dadx * dudx + a1w * d2ux + dady * dudy + a1w * d2uy;
    const float s_loss = sc * (phi * (dsw / dta) - (flux + finw));

    out[idx]     = p_loss;
    out[N + idx] = s_loss;
}

extern "C" void kernel_launch(void* const* d_in, const int* in_sizes, int n_in,
                              void* d_out, int out_size)
{
    const float* pressure = (const float*)d_in[0];
    const float* perm     = (const float*)d_in[1];
    const float* Q        = (const float*)d_in[2];
    const float* Qw       = (const float*)d_in[3];
    const float* Time     = (const float*)d_in[4];
    // d_in[5] = Pini — unused by the reference math
    const float* Phi      = (const float*)d_in[6];
    const float* Swini    = (const float*)d_in[7];
    const float* wsat     = (const float*)d_in[8];
    float* out = (float*)d_out;

    const int N = in_sizes[0];           // 5,242,880
    const int threads = 256;
    const int blocks = (N + threads - 1) / threads;
    blackoil_kernel<<<blocks, threads>>>(pressure, perm, Q, Qw, Time, Phi,
                                         Swini, wsat, out, N);
}

// round 2
// speedup vs baseline: 1.0704x; 1.0704x over previous
#include <cuda_runtime.h>

// Black_oil PINO residual, GB300 sm_103a — float4-vectorized over y.
// Shapes: [B=8, T=10, NZ=4, NX=128, NY=128], row-major, y contiguous.
// d_out: [p_loss (N floats) | s_loss (N floats)], N = 5,242,880.

#define TSTRIDE 65536   // NZ*NX*NY
#define NY 128
#define NV 32           // float4 vectors per row

__global__ __launch_bounds__(256)
void blackoil_kernel_v4(const float4* __restrict__ pr4,
                        const float4* __restrict__ perm4,
                        const float4* __restrict__ Q4,
                        const float4* __restrict__ Qw4,
                        const float4* __restrict__ Tm4,
                        const float4* __restrict__ Phi4,
                        const float* __restrict__ Swini,
                        const float4* __restrict__ ws4,
                        float4* __restrict__ out4,
                        int N4)
{
    const int v = blockIdx.x * blockDim.x + threadIdx.x;
    if (v >= N4) return;

    const int y4 = v & (NV - 1);            // vector index within row
    const int x  = (v >> 5) & 127;
    const int t  = (v >> 14) % 10;          // (b*10+t) % 10
    const int v0 = v - t * (TSTRIDE / 4);   // same (b,z,x,y) at t=0

    // x-stencil vector offsets (replicate clamp), units of float4 (row = 32 vecs)
    const int oxm = (x > 0)   ? -NV : 0;
    const int oxp = (x < 127) ?  NV : 0;

    const float* pr    = (const float*)pr4;
    const float* perm  = (const float*)perm4;

    // ---- pressure: center / x-neighbors / y-edge scalars ----
    const float4 uc4  = pr4[v];
    const float4 uxm4 = pr4[v + oxm];
    const float4 uxp4 = pr4[v + oxp];
    float uy[6];
    uy[1] = uc4.x; uy[2] = uc4.y; uy[3] = uc4.z; uy[4] = uc4.w;
    uy[0] = (y4 == 0)      ? uc4.x : pr[4 * v - 1];
    uy[5] = (y4 == NV - 1) ? uc4.w : pr[4 * v + 4];

    // ---- perm at t=0: center / x-neighbors / y-edge scalars ----
    const float4 p0c  = perm4[v0];
    const float4 p0xm = perm4[v0 + oxm];
    const float4 p0xp = perm4[v0 + oxp];
    float py[6];
    py[1] = p0c.x; py[2] = p0c.y; py[3] = p0c.z; py[4] = p0c.w;
    py[0] = (y4 == 0)      ? p0c.x : perm[4 * v0 - 1];
    py[5] = (y4 == NV - 1) ? p0c.w : perm[4 * v0 + 4];

    // ---- bulk per-point fields ----
    const float4 pc   = (t == 0) ? p0c : perm4[v];
    const float4 sat4 = ws4[v];
    const float  s0   = Swini[0];
    float4 prior4;
    if (t == 0) { prior4 = make_float4(s0, s0, s0, s0); }
    else        { prior4 = ws4[v - TSTRIDE / 4]; }
    const float4 q4   = Q4[v];
    const float4 qw4  = Qw4[v];
    const float4 tm4  = Tm4[v];
    const float4 ph4  = Phi4[v];

    // scalar mobility constants at Swini
    const float S0  = (s0 - 0.1f) * 1.25f;
    const float cW  = S0 * S0;
    const float cM  = cW + (1.0f - S0) * (1.0f - S0) * (1.0f / 2.75f);

    const float ucA[4]  = {uc4.x,  uc4.y,  uc4.z,  uc4.w};
    const float uxmA[4] = {uxm4.x, uxm4.y, uxm4.z, uxm4.w};
    const float uxpA[4] = {uxp4.x, uxp4.y, uxp4.z, uxp4.w};
    const float pxmA[4] = {p0xm.x, p0xm.y, p0xm.z, p0xm.w};
    const float pxpA[4] = {p0xp.x, p0xp.y, p0xp.z, p0xp.w};
    const float pcA[4]  = {pc.x,   pc.y,   pc.z,   pc.w};
    const float satA[4] = {sat4.x, sat4.y, sat4.z, sat4.w};
    const float priA[4] = {prior4.x, prior4.y, prior4.z, prior4.w};
    const float qA[4]   = {q4.x,   q4.y,   q4.z,   q4.w};
    const float qwA[4]  = {qw4.x,  qw4.y,  qw4.z,  qw4.w};
    const float tmA[4]  = {tm4.x,  tm4.y,  tm4.z,  tm4.w};
    const float phA[4]  = {ph4.x,  ph4.y,  ph4.z,  ph4.w};

    float plA[4], slA[4];

    #pragma unroll
    for (int i = 0; i < 4; i++) {
        // u = p*1000; d1 *64, d2 *16384 (h = 1/128)
        const float uc  = ucA[i]  * 1000.0f;
        const float uxm = uxmA[i] * 1000.0f;
        const float uxp = uxpA[i] * 1000.0f;
        const float uym = uy[i]     * 1000.0f;
        const float uyp = uy[i + 2] * 1000.0f;

        const float dudx = (uxp - uxm) * 64.0f;
        const float dudy = (uyp - uym) * 64.0f;
        const float d2ux = (uxp - 2.0f * uc + uxm) * 16384.0f;
        const float d2uy = (uyp - 2.0f * uc + uym) * 16384.0f;

        // a = 500*perm -> d1 scale 64*500 = 32000
        const float da0dx = (pxpA[i] - pxmA[i]) * 32000.0f;
        const float da0dy = (py[i + 2] - py[i]) * 32000.0f;

        const float prior = priA[i];
        const float dsw   = fmaxf(satA[i] - prior, 0.001f);
        const float S  = (prior - 0.1f) * 1.25f;
        const float Mw = S * S;
        const float Mo = (1.0f - S) * (1.0f - S) * (1.0f / 2.75f);
        const float aP  = 500.0f * pcA[i];
        const float a1  = (Mw + Mo) * aP;
        const float a1w = Mw * aP;

        const float fin  = qA[i]  * 5000.0f;
        const float finw = qwA[i] * 5000.0f;
        const float dta  = tmA[i] * 6000.0f;

        const float sc = 7.8125e-8f;   // (1/128)*1e-5
        plA[i] = sc * (fin + cM * da0dx * dudx + a1 * d2ux
                           + cM * da0dy * dudy + a1 * d2uy);
        const float flux = cW * da0dx * dudx + a1w * d2ux
                         + cW * da0dy * dudy + a1w * d2uy;
        slA[i] = sc * (phA[i] * (dsw / dta) - (flux + finw));
    }

    out4[v]      = make_float4(plA[0], plA[1], plA[2], plA[3]);
    out4[N4 + v] = make_float4(slA[0], slA[1], slA[2], slA[3]);
}

extern "C" void kernel_launch(void* const* d_in, const int* in_sizes, int n_in,
                              void* d_out, int out_size)
{
    const float4* pressure = (const float4*)d_in[0];
    const float4* perm     = (const float4*)d_in[1];
    const float4* Q        = (const float4*)d_in[2];
    const float4* Qw       = (const float4*)d_in[3];
    const float4* Time     = (const float4*)d_in[4];
    // d_in[5] = Pini — unused
    const float4* Phi      = (const float4*)d_in[6];
    const float*  Swini    = (const float*)d_in[7];
    const float4* wsat     = (const float4*)d_in[8];
    float4* out = (float4*)d_out;

    const int N4 = in_sizes[0] / 4;      // 1,310,720
    const int threads = 256;
    const int blocks = (N4 + threads - 1) / threads;
    blackoil_kernel_v4<<<blocks, threads>>>(pressure, perm, Q, Qw, Time, Phi,
                                            Swini, wsat, out, N4);
}

// round 3
// speedup vs baseline: 1.1629x; 1.0864x over previous
#include <cuda_runtime.h>

// Black_oil PINO residual, GB300 sm_103a — float4 over y, reduced register
// footprint (two-phase), streaming stores.
// Shapes: [B=8, T=10, NZ=4, NX=128, NY=128], row-major, y contiguous.
// d_out: [p_loss (N floats) | s_loss (N floats)], N = 5,242,880.

#define TS4 16384       // TSTRIDE/4 = (4*128*128)/4
#define NV  32          // float4 vectors per row

__global__ __launch_bounds__(256, 5)
void blackoil_kernel_v4b(const float4* __restrict__ pr4,
                         const float4* __restrict__ perm4,
                         const float4* __restrict__ Q4,
                         const float4* __restrict__ Qw4,
                         const float4* __restrict__ Tm4,
                         const float4* __restrict__ Phi4,
                         const float* __restrict__ Swini,
                         const float4* __restrict__ ws4,
                         float4* __restrict__ out4,
                         int N4)
{
    const int v = blockIdx.x * blockDim.x + threadIdx.x;
    if (v >= N4) return;

    const int y4 = v & (NV - 1);
    const int x  = (v >> 5) & 127;
    const int t  = (v >> 14) % 10;
    const int v0 = v - t * TS4;

    const int oxm = (x > 0)   ? -NV : 0;
    const int oxp = (x < 127) ?  NV : 0;

    const float* pr   = (const float*)pr4;
    const float* perm = (const float*)perm4;

    // scalar mobility constants at Swini
    const float s0 = Swini[0];
    const float S0 = (s0 - 0.1f) * 1.25f;
    const float cW = S0 * S0;
    const float cM = cW + (1.0f - S0) * (1.0f - S0) * (1.0f / 2.75f);

    // ---------- phase 1: stencils -> 5 small temporaries per lane ----------
    const float4 uc4  = pr4[v];
    const float4 uxm4 = pr4[v + oxm];
    const float4 uxp4 = pr4[v + oxp];
    const float  uL   = (y4 == 0)      ? uc4.x : pr[4 * v - 1];
    const float  uR   = (y4 == NV - 1) ? uc4.w : pr[4 * v + 4];

    const float4 p0c  = perm4[v0];
    const float4 p0xm = perm4[v0 + oxm];
    const float4 p0xp = perm4[v0 + oxp];
    const float  pL   = (y4 == 0)      ? p0c.x : perm[4 * v0 - 1];
    const float  pR   = (y4 == NV - 1) ? p0c.w : perm[4 * v0 + 4];

    const float4 pc     = (t == 0) ? p0c : perm4[v];
    const float4 prior4 = (t == 0) ? make_float4(s0, s0, s0, s0)
                                   : ws4[v - TS4];
    const float4 sat4   = ws4[v];

    float t1[4], t2[4], mwa[4], ma[4], dsw[4];

    {
        const float ucA[6]  = {uL, uc4.x, uc4.y, uc4.z, uc4.w, uR};
        const float pcA[6]  = {pL, p0c.x, p0c.y, p0c.z, p0c.w, pR};
        const float uxmA[4] = {uxm4.x, uxm4.y, uxm4.z, uxm4.w};
        const float uxpA[4] = {uxp4.x, uxp4.y, uxp4.z, uxp4.w};
        const float pxmA[4] = {p0xm.x, p0xm.y, p0xm.z, p0xm.w};
        const float pxpA[4] = {p0xp.x, p0xp.y, p0xp.z, p0xp.w};
        const float prA[4]  = {prior4.x, prior4.y, prior4.z, prior4.w};
        const float pmA[4]  = {pc.x, pc.y, pc.z, pc.w};
        const float stA[4]  = {sat4.x, sat4.y, sat4.z, sat4.w};

        #pragma unroll
        for (int i = 0; i < 4; i++) {
            // u = p*1000, h = 1/128: d1 scale 64*1000, d2 scale 16384*1000
            const float uc  = ucA[i + 1];
            const float dudx = (uxpA[i] - uxmA[i]) * 64000.0f;
            const float dudy = (ucA[i + 2] - ucA[i]) * 64000.0f;
            const float lap  = ((uxpA[i] - 2.0f * uc + uxmA[i])
                              + (ucA[i + 2] - 2.0f * uc + ucA[i])) * 16384000.0f;

            // a = 500*perm: d1 scale 64*500
            const float da0dx = (pxpA[i] - pxmA[i]) * 32000.0f;
            const float da0dy = (pcA[i + 2] - pcA[i]) * 32000.0f;

            t1[i] = da0dx * dudx + da0dy * dudy;
            t2[i] = lap;

            const float prior = prA[i];
            const float S  = (prior - 0.1f) * 1.25f;
            const float Mw = S * S;
            const float Mo = (1.0f - S) * (1.0f - S) * (1.0f / 2.75f);
            const float aP = 500.0f * pmA[i];
            mwa[i] = Mw * aP;
            ma[i]  = (Mw + Mo) * aP;
            dsw[i] = fmaxf(stA[i] - prior, 0.001f);
        }
    }

    const float sc = 7.8125e-8f;   // (1/128)*1e-5

    // ---------- phase 2a: p_loss ----------
    {
        const float4 q4 = Q4[v];
        float4 pl;
        pl.x = sc * (q4.x * 5000.0f + cM * t1[0] + ma[0] * t2[0]);
        pl.y = sc * (q4.y * 5000.0f + cM * t1[1] + ma[1] * t2[1]);
        pl.z = sc * (q4.z * 5000.0f + cM * t1[2] + ma[2] * t2[2]);
        pl.w = sc * (q4.w * 5000.0f + cM * t1[3] + ma[3] * t2[3]);
        __stcs(&out4[v], pl);
    }

    // ---------- phase 2b: s_loss ----------
    {
        const float4 qw4 = Qw4[v];
        const float4 tm4 = Tm4[v];
        const float4 ph4 = Phi4[v];
        float4 sl;
        sl.x = sc * (ph4.x * (dsw[0] / (tm4.x * 6000.0f))
                     - (cW * t1[0] + mwa[0] * t2[0] + qw4.x * 5000.0f));
        sl.y = sc * (ph4.y * (dsw[1] / (tm4.y * 6000.0f))
                     - (cW * t1[1] + mwa[1] * t2[1] + qw4.y * 5000.0f));
        sl.z = sc * (ph4.z * (dsw[2] / (tm4.z * 6000.0f))
                     - (cW * t1[2] + mwa[2] * t2[2] + qw4.z * 5000.0f));
        sl.w = sc * (ph4.w * (dsw[3] / (tm4.w * 6000.0f))
                     - (cW * t1[3] + mwa[3] * t2[3] + qw4.w * 5000.0f));
        __stcs(&out4[N4 + v], sl);
    }
}

extern "C" void kernel_launch(void* const* d_in, const int* in_sizes, int n_in,
                              void* d_out, int out_size)
{
    const float4* pressure = (const float4*)d_in[0];
    const float4* perm     = (const float4*)d_in[1];
    const float4* Q        = (const float4*)d_in[2];
    const float4* Qw       = (const float4*)d_in[3];
    const float4* Time     = (const float4*)d_in[4];
    // d_in[5] = Pini — unused
    const float4* Phi      = (const float4*)d_in[6];
    const float*  Swini    = (const float*)d_in[7];
    const float4* wsat     = (const float4*)d_in[8];
    float4* out = (float4*)d_out;

    const int N4 = in_sizes[0] / 4;      // 1,310,720
    const int threads = 256;
    const int blocks = (N4 + threads - 1) / threads;
    blackoil_kernel_v4b<<<blocks, threads>>>(pressure, perm, Q, Qw, Time, Phi,
                                             Swini, wsat, out, N4);
}